// round 6
// baseline (speedup 1.0000x reference)
#include <cuda_runtime.h>
#include <math.h>

// out[i,j] = | prod_k cos((x[i,k] - y[j,k]) / 2) |
// cos((a-b)/2) = cos(a/2)cos(b/2) + sin(a/2)sin(b/2)
// Fused __sincosf prologue -> f32x2-FMA mainloop. 64x128 tile, 4 CTAs/SM.

typedef unsigned long long u64;

__device__ __forceinline__ u64 fma2(u64 a, u64 b, u64 c) {
    u64 d;
    asm("fma.rn.f32x2 %0, %1, %2, %3;" : "=l"(d) : "l"(a), "l"(b), "l"(c));
    return d;
}
__device__ __forceinline__ u64 mul2(u64 a, u64 b) {
    u64 d;
    asm("mul.rn.f32x2 %0, %1, %2;" : "=l"(d) : "l"(a), "l"(b));
    return d;
}
__device__ __forceinline__ u64 dup2(float x) {
    u64 d;
    asm("mov.b64 %0, {%1, %2};" : "=l"(d) : "f"(x), "f"(x));
    return d;
}

// 64x128 tile per CTA, 256 threads, 4x8 outputs/thread (4x4 f32x2 pairs).
// Smem: x dup-pairs 16KB, y scalar 16KB = 32KB -> 4 CTAs/SM, 32 warps.
__global__ __launch_bounds__(256, 4)
void qk_fused(const float* __restrict__ x, const float* __restrict__ y,
              float* __restrict__ out, int n, int m) {
    __shared__ u64   s_xc[16][64];    // [k][i] = (cos,cos) of x/2   8KB
    __shared__ u64   s_xs[16][64];    // [k][i] = (sin,sin)          8KB
    __shared__ float s_yc[16][128];   // [k][j] = cos(y/2)           8KB
    __shared__ float s_ys[16][128];   // [k][j] = sin(y/2)           8KB

    const int tid = threadIdx.x;
    const int i0 = blockIdx.y * 64;
    const int j0 = blockIdx.x * 128;

    // Prologue: x tile (1024 values) then y tile (2048 values), r-fast mapping.
    #pragma unroll
    for (int c = 0; c < 4; c++) {
        int e = tid + 256 * c;        // 0..1023
        int r = e & 63, k = e >> 6;   // k in 0..15
        float sx, cx;
        __sincosf(0.5f * x[(i0 + r) * 16 + k], &sx, &cx);
        s_xc[k][r] = dup2(cx);
        s_xs[k][r] = dup2(sx);
    }
    #pragma unroll
    for (int c = 0; c < 8; c++) {
        int e = tid + 256 * c;        // 0..2047
        int r = e & 127, k = e >> 7;  // k in 0..15
        float sy, cy;
        __sincosf(0.5f * y[(j0 + r) * 16 + k], &sy, &cy);
        s_yc[k][r] = cy;
        s_ys[k][r] = sy;
    }
    __syncthreads();

    const int tx = tid & 15;   // j dimension (16 threads x 4 j-pairs)
    const int ty = tid >> 4;   // i dimension (16 threads x 4 i)

    u64 acc[4][4];
    const u64 ONE2 = 0x3f8000003f800000ULL;  // (1.0f, 1.0f)
    #pragma unroll
    for (int ii = 0; ii < 4; ii++)
        #pragma unroll
        for (int jj = 0; jj < 4; jj++) acc[ii][jj] = ONE2;

    #pragma unroll 4
    for (int k = 0; k < 16; k++) {
        u64 yc[4], ys[4];
        #pragma unroll
        for (int jj = 0; jj < 4; jj++) {
            // j-pair (2*tx, 2*tx+1) + 32*jj : conflict-free across tx
            yc[jj] = *(const u64*)&s_yc[k][2 * tx + 32 * jj];
            ys[jj] = *(const u64*)&s_ys[k][2 * tx + 32 * jj];
        }
        #pragma unroll
        for (int ii = 0; ii < 4; ii++) {
            u64 xc = s_xc[k][ty + 16 * ii];   // LDS.64 broadcast
            u64 xs = s_xs[k][ty + 16 * ii];
            #pragma unroll
            for (int jj = 0; jj < 4; jj++) {
                u64 t = fma2(xc, yc[jj], mul2(xs, ys[jj]));
                acc[ii][jj] = mul2(acc[ii][jj], t);
            }
        }
    }

    // abs via bitmask, 8B stores (coalesced per half-warp)
    #pragma unroll
    for (int ii = 0; ii < 4; ii++) {
        int i = i0 + ty + 16 * ii;
        float* orow = out + (size_t)i * m + j0;
        #pragma unroll
        for (int jj = 0; jj < 4; jj++) {
            u64 a = acc[ii][jj] & 0x7fffffff7fffffffULL;
            *(u64*)&orow[2 * tx + 32 * jj] = a;
        }
    }
}

// Generic fallback for unexpected shapes.
__global__ void qk_naive(const float* __restrict__ x, const float* __restrict__ y,
                         float* __restrict__ out, int n, int m, int d) {
    int j = blockIdx.x * blockDim.x + threadIdx.x;
    int i = blockIdx.y;
    if (i >= n || j >= m) return;
    float p = 1.0f;
    for (int k = 0; k < d; k++)
        p *= cosf(0.5f * (x[i * d + k] - y[j * d + k]));
    out[(size_t)i * m + j] = fabsf(p);
}

extern "C" void kernel_launch(void* const* d_in, const int* in_sizes, int n_in,
                              void* d_out, int out_size) {
    const float* x = (const float*)d_in[0];
    const float* y = (const float*)d_in[1];
    float* out = (float*)d_out;

    long long sx = in_sizes[0], sy = in_sizes[1], so = out_size;
    int d = (int)llround(sqrt((double)sx * (double)sy / (double)so));
    if (d <= 0) d = 16;
    int n = (int)(sx / d);
    int m = (int)(sy / d);

    if (d == 16 && n % 64 == 0 && m % 128 == 0) {
        dim3 grid(m / 128, n / 64);
        qk_fused<<<grid, 256>>>(x, y, out, n, m);
    } else {
        qk_naive<<<dim3((m + 255) / 256, n), 256>>>(x, y, out, n, m, d);
    }
}

// round 7
// speedup vs baseline: 1.1364x; 1.1364x over previous
#include <cuda_runtime.h>
#include <math.h>

// out[i,j] = | prod_k cos((x[i,k] - y[j,k]) / 2) |
// cos((a-b)/2) = cos(a/2)cos(b/2) + sin(a/2)sin(b/2)
// Fused __sincosf prologue -> f32x2-FMA mainloop with quad-packed smem:
//   x: ulonglong2 {(c,c),(s,s)}  -> 1 LDS.128 broadcast per ii
//   y: float4 {c0,c1,s0,s1}      -> 1 LDS.128 per jj (cos+sin pair together)

typedef unsigned long long u64;

__device__ __forceinline__ u64 fma2(u64 a, u64 b, u64 c) {
    u64 d;
    asm("fma.rn.f32x2 %0, %1, %2, %3;" : "=l"(d) : "l"(a), "l"(b), "l"(c));
    return d;
}
__device__ __forceinline__ u64 mul2(u64 a, u64 b) {
    u64 d;
    asm("mul.rn.f32x2 %0, %1, %2;" : "=l"(d) : "l"(a), "l"(b));
    return d;
}
__device__ __forceinline__ u64 dup2(float x) {
    u64 d;
    asm("mov.b64 %0, {%1, %2};" : "=l"(d) : "f"(x), "f"(x));
    return d;
}

// 128x128 tile per CTA, 256 threads, 8x8 outputs/thread (8x4 f32x2 pairs).
// Smem: x quads 32KB + y quads 16KB = 48KB -> 2 CTAs/SM.
__global__ __launch_bounds__(256, 2)
void qk_fused(const float* __restrict__ x, const float* __restrict__ y,
              float* __restrict__ out, int n, int m) {
    __shared__ __align__(16) ulonglong2 s_xq[16][128]; // [k][i] = {(c,c),(s,s)}
    __shared__ __align__(16) float      s_yq[16][256]; // [k][4p+{0,1,2,3}] = {c2p,c2p+1,s2p,s2p+1}

    const int tid = threadIdx.x;
    const int i0 = blockIdx.y * 128;
    const int j0 = blockIdx.x * 128;

    // Prologue: r-fast mapping; one sincos for x-tile, one for y-tile per (r,k).
    #pragma unroll
    for (int c = 0; c < 8; c++) {
        int e = tid + 256 * c;
        int r = e & 127, k = e >> 7;       // k in 0..15
        float sx, cx;
        __sincosf(0.5f * x[(i0 + r) * 16 + k], &sx, &cx);
        ulonglong2 q;
        q.x = dup2(cx);
        q.y = dup2(sx);
        s_xq[k][r] = q;
        float sy, cy;
        __sincosf(0.5f * y[(j0 + r) * 16 + k], &sy, &cy);
        int p = r >> 1, h = r & 1;
        s_yq[k][4 * p + h]     = cy;
        s_yq[k][4 * p + 2 + h] = sy;
    }
    __syncthreads();

    const int tx = tid & 15;   // j dimension (16 threads x 4 j-pairs)
    const int ty = tid >> 4;   // i dimension (16 threads x 8 i)

    u64 acc[8][4];
    const u64 ONE2 = 0x3f8000003f800000ULL;  // (1.0f, 1.0f)
    #pragma unroll
    for (int ii = 0; ii < 8; ii++)
        #pragma unroll
        for (int jj = 0; jj < 4; jj++) acc[ii][jj] = ONE2;

    #pragma unroll 4
    for (int k = 0; k < 16; k++) {
        // y: 4 LDS.128, each gives (cos-pair, sin-pair) for j-pair p = tx + 16*jj
        u64 yc[4], ys[4];
        #pragma unroll
        for (int jj = 0; jj < 4; jj++) {
            ulonglong2 q = *(const ulonglong2*)&s_yq[k][4 * (tx + 16 * jj)];
            yc[jj] = q.x;
            ys[jj] = q.y;
        }
        // x: 8 LDS.128 broadcast (2 addrs/warp), halves directly usable as u64
        #pragma unroll
        for (int ii = 0; ii < 8; ii++) {
            ulonglong2 xq = s_xq[k][ty + 16 * ii];
            #pragma unroll
            for (int jj = 0; jj < 4; jj++) {
                u64 t = fma2(xq.x, yc[jj], mul2(xq.y, ys[jj]));
                acc[ii][jj] = mul2(acc[ii][jj], t);
            }
        }
    }

    // abs via bitmask, 8B stores (coalesced per half-warp)
    #pragma unroll
    for (int ii = 0; ii < 8; ii++) {
        int i = i0 + ty + 16 * ii;
        float* orow = out + (size_t)i * m + j0;
        #pragma unroll
        for (int jj = 0; jj < 4; jj++) {
            u64 a = acc[ii][jj] & 0x7fffffff7fffffffULL;
            *(u64*)&orow[2 * tx + 32 * jj] = a;
        }
    }
}

// Generic fallback for unexpected shapes.
__global__ void qk_naive(const float* __restrict__ x, const float* __restrict__ y,
                         float* __restrict__ out, int n, int m, int d) {
    int j = blockIdx.x * blockDim.x + threadIdx.x;
    int i = blockIdx.y;
    if (i >= n || j >= m) return;
    float p = 1.0f;
    for (int k = 0; k < d; k++)
        p *= cosf(0.5f * (x[i * d + k] - y[j * d + k]));
    out[(size_t)i * m + j] = fabsf(p);
}

extern "C" void kernel_launch(void* const* d_in, const int* in_sizes, int n_in,
                              void* d_out, int out_size) {
    const float* x = (const float*)d_in[0];
    const float* y = (const float*)d_in[1];
    float* out = (float*)d_out;

    long long sx = in_sizes[0], sy = in_sizes[1], so = out_size;
    int d = (int)llround(sqrt((double)sx * (double)sy / (double)so));
    if (d <= 0) d = 16;
    int n = (int)(sx / d);
    int m = (int)(sy / d);

    if (d == 16 && n % 128 == 0 && m % 128 == 0) {
        dim3 grid(m / 128, n / 128);
        qk_fused<<<grid, 256>>>(x, y, out, n, m);
    } else {
        qk_naive<<<dim3((m + 255) / 256, n), 256>>>(x, y, out, n, m, d);
    }
}

// round 8
// speedup vs baseline: 1.4320x; 1.2601x over previous
#include <cuda_runtime.h>
#include <math.h>

// out[i,j] = | prod_k cos((x_ik - y_jk)/2) |
//          = | Px_i * Py_j * prod_k (1 + tan(x_ik/2) * tan(y_jk/2)) |
// where Px_i = prod_k cos(x_ik/2), Py_j = prod_k cos(y_jk/2).
// Inner loop: 1 fma2 + 1 mul2 per (i-pair, j-pair, k). Half the smem feed.

typedef unsigned long long u64;

__device__ __forceinline__ u64 fma2(u64 a, u64 b, u64 c) {
    u64 d;
    asm("fma.rn.f32x2 %0, %1, %2, %3;" : "=l"(d) : "l"(a), "l"(b), "l"(c));
    return d;
}
__device__ __forceinline__ u64 mul2(u64 a, u64 b) {
    u64 d;
    asm("mul.rn.f32x2 %0, %1, %2;" : "=l"(d) : "l"(a), "l"(b));
    return d;
}
__device__ __forceinline__ u64 dup2(float x) {
    u64 d;
    asm("mov.b64 %0, {%1, %2};" : "=l"(d) : "f"(x), "f"(x));
    return d;
}

// 128x128 tile per CTA, 256 threads, 8x8 outputs/thread (8x4 f32x2 pairs).
// Smem ~26KB -> 2 CTAs/SM (regs are the real cap anyway).
__global__ __launch_bounds__(256, 2)
void qk_fused(const float* __restrict__ x, const float* __restrict__ y,
              float* __restrict__ out, int n, int m) {
    __shared__ u64   s_xt[16][128];  // [k][i] = (tanx, tanx)  16KB
    __shared__ float s_yt[16][128];  // [k][j] = tany           8KB
    __shared__ u64   s_px[128];      // (Px_i, Px_i)            1KB
    __shared__ float s_py[128];      // Py_j                    0.5KB

    const int tid = threadIdx.x;
    const int i0 = blockIdx.y * 128;
    const int j0 = blockIdx.x * 128;

    // Prologue: thread t<128 handles x-row t; t>=128 handles y-row t-128.
    {
        int r = tid & 127;
        bool isx = tid < 128;
        const float* src = isx ? (x + (size_t)(i0 + r) * 16)
                               : (y + (size_t)(j0 + r) * 16);
        float4 v0 = ((const float4*)src)[0];
        float4 v1 = ((const float4*)src)[1];
        float4 v2 = ((const float4*)src)[2];
        float4 v3 = ((const float4*)src)[3];
        float vv[16] = {v0.x, v0.y, v0.z, v0.w, v1.x, v1.y, v1.z, v1.w,
                        v2.x, v2.y, v2.z, v2.w, v3.x, v3.y, v3.z, v3.w};
        float prod = 1.0f;
        #pragma unroll
        for (int k = 0; k < 16; k++) {
            float s, c;
            __sincosf(0.5f * vv[k], &s, &c);
            prod *= c;
            float t = __fdividef(s, c);
            if (isx) s_xt[k][r] = dup2(t);
            else     s_yt[k][r] = t;
        }
        if (isx) s_px[r] = dup2(prod);
        else     s_py[r] = prod;
    }
    __syncthreads();

    const int tx = tid & 15;   // j dimension (16 threads x 4 j-pairs)
    const int ty = tid >> 4;   // i dimension (16 threads x 8 i)

    u64 acc[8][4];
    const u64 ONE2 = 0x3f8000003f800000ULL;  // (1.0f, 1.0f)
    #pragma unroll
    for (int ii = 0; ii < 8; ii++)
        #pragma unroll
        for (int jj = 0; jj < 4; jj++) acc[ii][jj] = ONE2;

    #pragma unroll 4
    for (int k = 0; k < 16; k++) {
        u64 yt[4];
        #pragma unroll
        for (int jj = 0; jj < 4; jj++)
            yt[jj] = *(const u64*)&s_yt[k][2 * tx + 32 * jj];  // conflict-free
        #pragma unroll
        for (int ii = 0; ii < 8; ii++) {
            u64 xt = s_xt[k][ty + 16 * ii];   // LDS.64 broadcast
            #pragma unroll
            for (int jj = 0; jj < 4; jj++)
                acc[ii][jj] = mul2(acc[ii][jj], fma2(xt, yt[jj], ONE2));
        }
    }

    // Epilogue: scale by Px_i * Py_j, abs via bitmask, 8B coalesced stores.
    u64 py[4];
    #pragma unroll
    for (int jj = 0; jj < 4; jj++)
        py[jj] = *(const u64*)&s_py[2 * tx + 32 * jj];
    #pragma unroll
    for (int ii = 0; ii < 8; ii++) {
        int i = i0 + ty + 16 * ii;
        u64 px = s_px[ty + 16 * ii];
        float* orow = out + (size_t)i * m + j0;
        #pragma unroll
        for (int jj = 0; jj < 4; jj++) {
            u64 v = mul2(mul2(acc[ii][jj], px), py[jj]);
            *(u64*)&orow[2 * tx + 32 * jj] = v & 0x7fffffff7fffffffULL;
        }
    }
}

// Generic fallback for unexpected shapes.
__global__ void qk_naive(const float* __restrict__ x, const float* __restrict__ y,
                         float* __restrict__ out, int n, int m, int d) {
    int j = blockIdx.x * blockDim.x + threadIdx.x;
    int i = blockIdx.y;
    if (i >= n || j >= m) return;
    float p = 1.0f;
    for (int k = 0; k < d; k++)
        p *= cosf(0.5f * (x[i * d + k] - y[j * d + k]));
    out[(size_t)i * m + j] = fabsf(p);
}

extern "C" void kernel_launch(void* const* d_in, const int* in_sizes, int n_in,
                              void* d_out, int out_size) {
    const float* x = (const float*)d_in[0];
    const float* y = (const float*)d_in[1];
    float* out = (float*)d_out;

    long long sx = in_sizes[0], sy = in_sizes[1], so = out_size;
    int d = (int)llround(sqrt((double)sx * (double)sy / (double)so));
    if (d <= 0) d = 16;
    int n = (int)(sx / d);
    int m = (int)(sy / d);

    if (d == 16 && n % 128 == 0 && m % 128 == 0) {
        dim3 grid(m / 128, n / 128);
        qk_fused<<<grid, 256>>>(x, y, out, n, m);
    } else {
        qk_naive<<<dim3((m + 255) / 256, n), 256>>>(x, y, out, n, m, d);
    }
}

// round 9
// speedup vs baseline: 1.5038x; 1.0501x over previous
#include <cuda_runtime.h>
#include <math.h>

// out[i,j] = | prod_k cos((x_ik - y_jk)/2) |
//          = | Px_i * Py_j * prod_k (1 + tan(x_ik/2) * tan(y_jk/2)) |
// 128x128 tile, 512 threads/CTA (32 outputs/thread) -> 2 CTAs/SM = 32 warps.

typedef unsigned long long u64;

__device__ __forceinline__ u64 fma2(u64 a, u64 b, u64 c) {
    u64 d;
    asm("fma.rn.f32x2 %0, %1, %2, %3;" : "=l"(d) : "l"(a), "l"(b), "l"(c));
    return d;
}
__device__ __forceinline__ u64 mul2(u64 a, u64 b) {
    u64 d;
    asm("mul.rn.f32x2 %0, %1, %2;" : "=l"(d) : "l"(a), "l"(b));
    return d;
}
__device__ __forceinline__ u64 dup2(float x) {
    u64 d;
    asm("mov.b64 %0, {%1, %2};" : "=l"(d) : "f"(x), "f"(x));
    return d;
}

__global__ __launch_bounds__(512, 2)
void qk_fused(const float* __restrict__ x, const float* __restrict__ y,
              float* __restrict__ out, int n, int m) {
    __shared__ u64   s_xt[16][128];   // [k][i] = (tanx, tanx)  16KB
    __shared__ float s_yt[16][128];   // [k][j] = tany           8KB
    __shared__ u64   s_px[128];       // (Px_i, Px_i)            1KB
    __shared__ float s_py[128];       // Py_j                    0.5KB
    __shared__ float s_part[256][2];  // per-row half-products   2KB

    const int tid = threadIdx.x;
    const int i0 = blockIdx.y * 128;
    const int j0 = blockIdx.x * 128;

    // Prologue: 512 threads, each does 8 sincos (row r, k-half h).
    {
        int r = tid & 255;            // 0..127: x-row, 128..255: y-row
        int h = tid >> 8;             // k in [8h, 8h+8)
        bool isx = r < 128;
        int rr = r & 127;
        const float* src = isx ? (x + (size_t)(i0 + rr) * 16)
                               : (y + (size_t)(j0 + rr) * 16);
        float4 v0 = ((const float4*)src)[2 * h];
        float4 v1 = ((const float4*)src)[2 * h + 1];
        float vv[8] = {v0.x, v0.y, v0.z, v0.w, v1.x, v1.y, v1.z, v1.w};
        float prod = 1.0f;
        #pragma unroll
        for (int q = 0; q < 8; q++) {
            int k = 8 * h + q;
            float s, c;
            __sincosf(0.5f * vv[q], &s, &c);
            prod *= c;
            float t = __fdividef(s, c);
            if (isx) s_xt[k][rr] = dup2(t);
            else     s_yt[k][rr] = t;
        }
        s_part[r][h] = prod;
    }
    __syncthreads();
    if (tid < 256) {
        int r = tid;
        float p = s_part[r][0] * s_part[r][1];
        if (r < 128) s_px[r] = dup2(p);
        else         s_py[r - 128] = p;
    }
    __syncthreads();

    const int tx = tid & 15;   // j: 4 pairs at 2*tx + 32*jj
    const int ty = tid >> 4;   // i: 0..31, rows ty + 32*ii

    u64 acc[4][4];
    const u64 ONE2 = 0x3f8000003f800000ULL;
    #pragma unroll
    for (int ii = 0; ii < 4; ii++)
        #pragma unroll
        for (int jj = 0; jj < 4; jj++) acc[ii][jj] = ONE2;

    #pragma unroll
    for (int k = 0; k < 16; k++) {
        u64 yt[4];
        #pragma unroll
        for (int jj = 0; jj < 4; jj++)
            yt[jj] = *(const u64*)&s_yt[k][2 * tx + 32 * jj];  // broadcast-safe
        #pragma unroll
        for (int ii = 0; ii < 4; ii++) {
            u64 xt = s_xt[k][ty + 32 * ii];                    // LDS.64 broadcast
            #pragma unroll
            for (int jj = 0; jj < 4; jj++)
                acc[ii][jj] = mul2(acc[ii][jj], fma2(xt, yt[jj], ONE2));
        }
    }

    // Epilogue: scale by Px_i * Py_j, abs, 8B coalesced stores.
    u64 py[4];
    #pragma unroll
    for (int jj = 0; jj < 4; jj++)
        py[jj] = *(const u64*)&s_py[2 * tx + 32 * jj];
    #pragma unroll
    for (int ii = 0; ii < 4; ii++) {
        int i = i0 + ty + 32 * ii;
        u64 px = s_px[ty + 32 * ii];
        float* orow = out + (size_t)i * m + j0;
        #pragma unroll
        for (int jj = 0; jj < 4; jj++) {
            u64 v = mul2(mul2(acc[ii][jj], px), py[jj]);
            *(u64*)&orow[2 * tx + 32 * jj] = v & 0x7fffffff7fffffffULL;
        }
    }
}

// Generic fallback for unexpected shapes.
__global__ void qk_naive(const float* __restrict__ x, const float* __restrict__ y,
                         float* __restrict__ out, int n, int m, int d) {
    int j = blockIdx.x * blockDim.x + threadIdx.x;
    int i = blockIdx.y;
    if (i >= n || j >= m) return;
    float p = 1.0f;
    for (int k = 0; k < d; k++)
        p *= cosf(0.5f * (x[i * d + k] - y[j * d + k]));
    out[(size_t)i * m + j] = fabsf(p);
}

extern "C" void kernel_launch(void* const* d_in, const int* in_sizes, int n_in,
                              void* d_out, int out_size) {
    const float* x = (const float*)d_in[0];
    const float* y = (const float*)d_in[1];
    float* out = (float*)d_out;

    long long sx = in_sizes[0], sy = in_sizes[1], so = out_size;
    int d = (int)llround(sqrt((double)sx * (double)sy / (double)so));
    if (d <= 0) d = 16;
    int n = (int)(sx / d);
    int m = (int)(sy / d);

    if (d == 16 && n % 128 == 0 && m % 128 == 0) {
        dim3 grid(m / 128, n / 128);
        qk_fused<<<grid, 512>>>(x, y, out, n, m);
    } else {
        qk_naive<<<dim3((m + 255) / 256, n), 256>>>(x, y, out, n, m, d);
    }
}

// round 10
// speedup vs baseline: 1.5075x; 1.0025x over previous
#include <cuda_runtime.h>
#include <math.h>

// out[i,j] = | prod_k cos((x_ik - y_jk)/2) |
//          = | Px_i * Py_j * prod_k (1 + tan(x_ik/2) * tan(y_jk/2)) |
// Mainloop update: p = x*y (rt2), acc = fma(acc, p, acc) (2 distinct pairs -> rt2).

typedef unsigned long long u64;

__device__ __forceinline__ u64 fma2(u64 a, u64 b, u64 c) {
    u64 d;
    asm("fma.rn.f32x2 %0, %1, %2, %3;" : "=l"(d) : "l"(a), "l"(b), "l"(c));
    return d;
}
__device__ __forceinline__ u64 mul2(u64 a, u64 b) {
    u64 d;
    asm("mul.rn.f32x2 %0, %1, %2;" : "=l"(d) : "l"(a), "l"(b));
    return d;
}
__device__ __forceinline__ u64 dup2(float x) {
    u64 d;
    asm("mov.b64 %0, {%1, %2};" : "=l"(d) : "f"(x), "f"(x));
    return d;
}

__global__ __launch_bounds__(512, 2)
void qk_fused(const float* __restrict__ x, const float* __restrict__ y,
              float* __restrict__ out, int n, int m) {
    __shared__ u64   s_xt[16][128];   // [k][i] = (tanx, tanx)  16KB
    __shared__ float s_yt[16][128];   // [k][j] = tany           8KB
    __shared__ u64   s_px[128];       // (Px_i, Px_i)            1KB
    __shared__ float s_py[128];       // Py_j                    0.5KB
    __shared__ float s_part[256][2];  // per-row half-products   2KB

    const int tid = threadIdx.x;
    const int i0 = blockIdx.y * 128;
    const int j0 = blockIdx.x * 128;

    // Prologue: 512 threads, each does 8 sincos (row r, k-half h).
    {
        int r = tid & 255;            // 0..127: x-row, 128..255: y-row
        int h = tid >> 8;             // k in [8h, 8h+8)
        bool isx = r < 128;
        int rr = r & 127;
        const float* src = isx ? (x + (size_t)(i0 + rr) * 16)
                               : (y + (size_t)(j0 + rr) * 16);
        float4 v0 = ((const float4*)src)[2 * h];
        float4 v1 = ((const float4*)src)[2 * h + 1];
        float vv[8] = {v0.x, v0.y, v0.z, v0.w, v1.x, v1.y, v1.z, v1.w};
        float prod = 1.0f;
        #pragma unroll
        for (int q = 0; q < 8; q++) {
            int k = 8 * h + q;
            float s, c;
            __sincosf(0.5f * vv[q], &s, &c);
            prod *= c;
            float t = __fdividef(s, c);
            if (isx) s_xt[k][rr] = dup2(t);
            else     s_yt[k][rr] = t;
        }
        s_part[r][h] = prod;
    }
    __syncthreads();
    if (tid < 256) {
        int r = tid;
        float p = s_part[r][0] * s_part[r][1];
        if (r < 128) s_px[r] = dup2(p);
        else         s_py[r - 128] = p;
    }
    __syncthreads();

    const int tx = tid & 15;   // j: 4 pairs at 2*tx + 32*jj
    const int ty = tid >> 4;   // i: rows ty + 32*ii

    u64 acc[4][4];
    const u64 ONE2 = 0x3f8000003f800000ULL;
    #pragma unroll
    for (int ii = 0; ii < 4; ii++)
        #pragma unroll
        for (int jj = 0; jj < 4; jj++) acc[ii][jj] = ONE2;

    #pragma unroll
    for (int k = 0; k < 16; k++) {
        // Batch all loads for this k up front (scoreboard drains once per k).
        u64 yt[4], xt[4];
        #pragma unroll
        for (int jj = 0; jj < 4; jj++)
            yt[jj] = *(const u64*)&s_yt[k][2 * tx + 32 * jj];
        #pragma unroll
        for (int ii = 0; ii < 4; ii++)
            xt[ii] = s_xt[k][ty + 32 * ii];
        #pragma unroll
        for (int ii = 0; ii < 4; ii++)
            #pragma unroll
            for (int jj = 0; jj < 4; jj++) {
                u64 p = mul2(xt[ii], yt[jj]);           // rt 2
                acc[ii][jj] = fma2(acc[ii][jj], p, acc[ii][jj]);  // rt 2
            }
    }

    // Epilogue: scale by Px_i * Py_j, abs, 8B coalesced stores.
    u64 py[4];
    #pragma unroll
    for (int jj = 0; jj < 4; jj++)
        py[jj] = *(const u64*)&s_py[2 * tx + 32 * jj];
    #pragma unroll
    for (int ii = 0; ii < 4; ii++) {
        int i = i0 + ty + 32 * ii;
        u64 px = s_px[ty + 32 * ii];
        float* orow = out + (size_t)i * m + j0;
        #pragma unroll
        for (int jj = 0; jj < 4; jj++) {
            u64 v = mul2(mul2(acc[ii][jj], px), py[jj]);
            *(u64*)&orow[2 * tx + 32 * jj] = v & 0x7fffffff7fffffffULL;
        }
    }
}

// Generic fallback for unexpected shapes.
__global__ void qk_naive(const float* __restrict__ x, const float* __restrict__ y,
                         float* __restrict__ out, int n, int m, int d) {
    int j = blockIdx.x * blockDim.x + threadIdx.x;
    int i = blockIdx.y;
    if (i >= n || j >= m) return;
    float p = 1.0f;
    for (int k = 0; k < d; k++)
        p *= cosf(0.5f * (x[i * d + k] - y[j * d + k]));
    out[(size_t)i * m + j] = fabsf(p);
}

extern "C" void kernel_launch(void* const* d_in, const int* in_sizes, int n_in,
                              void* d_out, int out_size) {
    const float* x = (const float*)d_in[0];
    const float* y = (const float*)d_in[1];
    float* out = (float*)d_out;

    long long sx = in_sizes[0], sy = in_sizes[1], so = out_size;
    int d = (int)llround(sqrt((double)sx * (double)sy / (double)so));
    if (d <= 0) d = 16;
    int n = (int)(sx / d);
    int m = (int)(sy / d);

    if (d == 16 && n % 128 == 0 && m % 128 == 0) {
        dim3 grid(m / 128, n / 128);
        qk_fused<<<grid, 512>>>(x, y, out, n, m);
    } else {
        qk_naive<<<dim3((m + 255) / 256, n), 256>>>(x, y, out, n, m, d);
    }
}